// round 1
// baseline (speedup 1.0000x reference)
#include <cuda_runtime.h>

// Problem constants (fixed by the reference setup_inputs)
#define BATCH 8
#define HH 512
#define WW 512
#define PLANE (HH * WW)          // 262144
#define NP (BATCH * PLANE)       // 2097152 elems per single-channel stack
#define RAD 15                   // radius
#define KK 31                    // kernel width
#define INV_K2 (1.0f / 961.0f)
#define EPSV 1e-6f

// -------- scratch (device globals; no allocation allowed) --------
// quantities (stage 1): 0=I, 1=I*I, 2..4=p_c, 5..7=I*p_c
__device__ float g_gray[NP];          // 8 MB
__device__ float g_hsum[8][NP];       // 64 MB  (horizontal box sums, stage 1)
__device__ float g_ab[6][NP];         // 48 MB  (a_r,a_g,a_b,b_r,b_g,b_b)
__device__ float g_hsum2[6][NP];      // 48 MB  (horizontal box sums of a,b)

// -------- warp inclusive scan --------
__device__ __forceinline__ float iscan(float v, int lane) {
#pragma unroll
    for (int o = 1; o < 32; o <<= 1) {
        float n = __shfl_up_sync(0xffffffffu, v, o);
        if (lane >= o) v += n;
    }
    return v;
}

// ============================================================================
// K1: horizontal pass on stage-1 quantities.
// 1 warp per image row; 4 rows per block (128 threads).
// For each quantity: warp-scan prefix into smem, then hsum[x] = pref[min(x+15,511)] - pref[x-16].
// ============================================================================
__global__ __launch_bounds__(128) void k_h1(const float* __restrict__ guide,
                                            const float* __restrict__ input) {
    const int warp = threadIdx.x >> 5;
    const int lane = threadIdx.x & 31;
    const int grow = blockIdx.x * 4 + warp;     // global row id in [0, BATCH*HH)
    const int b = grow >> 9;
    const int r = grow & 511;

    const float* gR = guide + ((size_t)(b * 3 + 0) * HH + r) * WW;
    const float* gG = guide + ((size_t)(b * 3 + 1) * HH + r) * WW;
    const float* gB = guide + ((size_t)(b * 3 + 2) * HH + r) * WW;
    const float* p0 = input + ((size_t)(b * 3 + 0) * HH + r) * WW;
    const float* p1 = input + ((size_t)(b * 3 + 1) * HH + r) * WW;
    const float* p2 = input + ((size_t)(b * 3 + 2) * HH + r) * WW;

    __shared__ float s_gray[4][WW];
    __shared__ float s_pref[4][WW];
    float* gray = s_gray[warp];
    float* pref = s_pref[warp];

    const size_t rowOff = (size_t)grow * WW;    // == b*PLANE + r*WW

    // grayscale row (also persisted for K4)
#pragma unroll
    for (int i = 0; i < 16; i++) {
        int c = i * 32 + lane;
        float v = 0.299f * gR[c] + 0.587f * gG[c] + 0.114f * gB[c];
        gray[c] = v;
        g_gray[rowOff + c] = v;
    }
    __syncwarp();

    auto run_q = [&](auto getv, float* __restrict__ outp) {
        float carry = 0.f;
#pragma unroll
        for (int i = 0; i < 16; i++) {
            int c = i * 32 + lane;
            float s = iscan(getv(c), lane);
            pref[c] = s + carry;
            carry += __shfl_sync(0xffffffffu, s, 31);
        }
        __syncwarp();
#pragma unroll
        for (int i = 0; i < 16; i++) {
            int c = i * 32 + lane;
            float hi = pref[(c + RAD > WW - 1) ? (WW - 1) : (c + RAD)];
            float lo = (c >= RAD + 1) ? pref[c - RAD - 1] : 0.f;
            outp[c] = hi - lo;
        }
        __syncwarp();
    };

    run_q([&](int c) { return gray[c]; },            g_hsum[0] + rowOff);
    run_q([&](int c) { float g = gray[c]; return g * g; }, g_hsum[1] + rowOff);
    run_q([&](int c) { return p0[c]; },              g_hsum[2] + rowOff);
    run_q([&](int c) { return p1[c]; },              g_hsum[3] + rowOff);
    run_q([&](int c) { return p2[c]; },              g_hsum[4] + rowOff);
    run_q([&](int c) { return gray[c] * p0[c]; },    g_hsum[5] + rowOff);
    run_q([&](int c) { return gray[c] * p1[c]; },    g_hsum[6] + rowOff);
    run_q([&](int c) { return gray[c] * p2[c]; },    g_hsum[7] + rowOff);
}

// ============================================================================
// K2: vertical running sums on the 8 hsum planes + fused a,b computation.
// Thread = one column; block = 128 columns; 64-row segment per block (y),
// batch on z. Init window [r0-15, r0+15], then slide.
// ============================================================================
__global__ __launch_bounds__(128) void k_v1() {
    const int col = blockIdx.x * 128 + threadIdx.x;
    const int b   = blockIdx.z;
    const int r0  = blockIdx.y * 64;
    const size_t base = (size_t)b * PLANE + col;

    float s[8];
#pragma unroll
    for (int q = 0; q < 8; q++) s[q] = 0.f;

    for (int j = r0 - RAD; j <= r0 + RAD; j++) {
        if (j >= 0) {   // j <= r0+15 <= 463+15 < 512 always for r0 <= 448
            size_t off = base + (size_t)j * WW;
#pragma unroll
            for (int q = 0; q < 8; q++) s[q] += g_hsum[q][off];
        }
    }

    for (int i = 0; i < 64; i++) {
        const int row = r0 + i;
        const size_t off = base + (size_t)row * WW;

        float mI = s[0] * INV_K2;
        float cI = s[1] * INV_K2;
        float invv = 1.f / (cI - mI * mI + EPSV);
#pragma unroll
        for (int c = 0; c < 3; c++) {
            float mp  = s[2 + c] * INV_K2;
            float cIp = s[5 + c] * INV_K2;
            float a   = (cIp - mI * mp) * invv;
            float bb  = mp - a * mI;
            g_ab[c][off]     = a;
            g_ab[3 + c][off] = bb;
        }

        int lead  = row + RAD + 1;
        int trail = row - RAD;
        if (lead < HH) {
            size_t lo = base + (size_t)lead * WW;
#pragma unroll
            for (int q = 0; q < 8; q++) s[q] += g_hsum[q][lo];
        }
        if (trail >= 0) {
            size_t to = base + (size_t)trail * WW;
#pragma unroll
            for (int q = 0; q < 8; q++) s[q] -= g_hsum[q][to];
        }
    }
}

// ============================================================================
// K3: generic horizontal pass on a,b planes (6 quantities on blockIdx.y).
// ============================================================================
__global__ __launch_bounds__(128) void k_h2() {
    const int warp = threadIdx.x >> 5;
    const int lane = threadIdx.x & 31;
    const int grow = blockIdx.x * 4 + warp;
    const int q = blockIdx.y;

    __shared__ float s_pref[4][WW];
    float* pref = s_pref[warp];

    const size_t rowOff = (size_t)grow * WW;
    const float* __restrict__ in = g_ab[q] + rowOff;
    float* __restrict__ out = g_hsum2[q] + rowOff;

    float carry = 0.f;
#pragma unroll
    for (int i = 0; i < 16; i++) {
        int c = i * 32 + lane;
        float s = iscan(in[c], lane);
        pref[c] = s + carry;
        carry += __shfl_sync(0xffffffffu, s, 31);
    }
    __syncwarp();
#pragma unroll
    for (int i = 0; i < 16; i++) {
        int c = i * 32 + lane;
        float hi = pref[(c + RAD > WW - 1) ? (WW - 1) : (c + RAD)];
        float lo = (c >= RAD + 1) ? pref[c - RAD - 1] : 0.f;
        out[c] = hi - lo;
    }
}

// ============================================================================
// K4: vertical running sums on hsum2 (6 planes) + fused final output.
// out[b,c,row,col] = mean_a_c * gray + mean_b_c
// ============================================================================
__global__ __launch_bounds__(128) void k_v2(float* __restrict__ out) {
    const int col = blockIdx.x * 128 + threadIdx.x;
    const int b   = blockIdx.z;
    const int r0  = blockIdx.y * 64;
    const size_t base = (size_t)b * PLANE + col;

    float s[6];
#pragma unroll
    for (int q = 0; q < 6; q++) s[q] = 0.f;

    for (int j = r0 - RAD; j <= r0 + RAD; j++) {
        if (j >= 0) {
            size_t off = base + (size_t)j * WW;
#pragma unroll
            for (int q = 0; q < 6; q++) s[q] += g_hsum2[q][off];
        }
    }

    for (int i = 0; i < 64; i++) {
        const int row = r0 + i;
        const size_t off = base + (size_t)row * WW;
        const float gr = g_gray[off];
#pragma unroll
        for (int c = 0; c < 3; c++) {
            float ma = s[c] * INV_K2;
            float mb = s[3 + c] * INV_K2;
            out[((size_t)(b * 3 + c) * HH + row) * WW + col] = ma * gr + mb;
        }

        int lead  = row + RAD + 1;
        int trail = row - RAD;
        if (lead < HH) {
            size_t lo = base + (size_t)lead * WW;
#pragma unroll
            for (int q = 0; q < 6; q++) s[q] += g_hsum2[q][lo];
        }
        if (trail >= 0) {
            size_t to = base + (size_t)trail * WW;
#pragma unroll
            for (int q = 0; q < 6; q++) s[q] -= g_hsum2[q][to];
        }
    }
}

// ============================================================================
extern "C" void kernel_launch(void* const* d_in, const int* in_sizes, int n_in,
                              void* d_out, int out_size) {
    const float* guide = (const float*)d_in[0];
    const float* input = (const float*)d_in[1];
    float* out = (float*)d_out;

    k_h1<<<BATCH * HH / 4, 128>>>(guide, input);
    k_v1<<<dim3(WW / 128, HH / 64, BATCH), 128>>>();
    k_h2<<<dim3(BATCH * HH / 4, 6), 128>>>();
    k_v2<<<dim3(WW / 128, HH / 64, BATCH), 128>>>(out);
}

// round 2
// speedup vs baseline: 1.8376x; 1.8376x over previous
#include <cuda_runtime.h>

// Problem constants (fixed by the reference setup_inputs)
#define BATCH 8
#define HH 512
#define WW 512
#define W2 (WW / 2)
#define PLANE (HH * WW)          // 262144
#define NP (BATCH * PLANE)       // 2097152 elems per single-channel stack
#define RAD 15
#define INV_K2 (1.0f / 961.0f)
#define EPSV 1e-6f
#define SEG 16                   // rows per vertical segment

// -------- scratch (device globals; no allocation allowed) --------
// stage-1 quantities: 0=I, 1=I*I, 2..4=p_c, 5..7=I*p_c
__device__ float g_gray[NP];          // 8 MB
__device__ float g_hsum[8][NP];       // 64 MB  (horizontal box sums, stage 1)
__device__ float g_ab[6][NP];         // 48 MB  (a_r,a_g,a_b,b_r,b_g,b_b)
__device__ float g_hsum2[6][NP];      // 48 MB  (horizontal box sums of a,b)

// -------- warp inclusive scan --------
__device__ __forceinline__ float iscan(float v, int lane) {
#pragma unroll
    for (int o = 1; o < 32; o <<= 1) {
        float n = __shfl_up_sync(0xffffffffu, v, o);
        if (lane >= o) v += n;
    }
    return v;
}

// ============================================================================
// K1: horizontal pass on stage-1 quantities (1 warp per row, 4 rows/block).
// ============================================================================
__global__ __launch_bounds__(128) void k_h1(const float* __restrict__ guide,
                                            const float* __restrict__ input) {
    const int warp = threadIdx.x >> 5;
    const int lane = threadIdx.x & 31;
    const int grow = blockIdx.x * 4 + warp;
    const int b = grow >> 9;
    const int r = grow & 511;

    const float* gR = guide + ((size_t)(b * 3 + 0) * HH + r) * WW;
    const float* gG = guide + ((size_t)(b * 3 + 1) * HH + r) * WW;
    const float* gB = guide + ((size_t)(b * 3 + 2) * HH + r) * WW;
    const float* p0 = input + ((size_t)(b * 3 + 0) * HH + r) * WW;
    const float* p1 = input + ((size_t)(b * 3 + 1) * HH + r) * WW;
    const float* p2 = input + ((size_t)(b * 3 + 2) * HH + r) * WW;

    __shared__ float s_gray[4][WW];
    __shared__ float s_pref[4][WW];
    float* gray = s_gray[warp];
    float* pref = s_pref[warp];

    const size_t rowOff = (size_t)grow * WW;

#pragma unroll
    for (int i = 0; i < 16; i++) {
        int c = i * 32 + lane;
        float v = 0.299f * gR[c] + 0.587f * gG[c] + 0.114f * gB[c];
        gray[c] = v;
        g_gray[rowOff + c] = v;
    }
    __syncwarp();

    auto run_q = [&](auto getv, float* __restrict__ outp) {
        float carry = 0.f;
#pragma unroll
        for (int i = 0; i < 16; i++) {
            int c = i * 32 + lane;
            float s = iscan(getv(c), lane);
            pref[c] = s + carry;
            carry += __shfl_sync(0xffffffffu, s, 31);
        }
        __syncwarp();
#pragma unroll
        for (int i = 0; i < 16; i++) {
            int c = i * 32 + lane;
            float hi = pref[(c + RAD > WW - 1) ? (WW - 1) : (c + RAD)];
            float lo = (c >= RAD + 1) ? pref[c - RAD - 1] : 0.f;
            outp[c] = hi - lo;
        }
        __syncwarp();
    };

    run_q([&](int c) { return gray[c]; },                  g_hsum[0] + rowOff);
    run_q([&](int c) { float g = gray[c]; return g * g; }, g_hsum[1] + rowOff);
    run_q([&](int c) { return p0[c]; },                    g_hsum[2] + rowOff);
    run_q([&](int c) { return p1[c]; },                    g_hsum[3] + rowOff);
    run_q([&](int c) { return p2[c]; },                    g_hsum[4] + rowOff);
    run_q([&](int c) { return gray[c] * p0[c]; },          g_hsum[5] + rowOff);
    run_q([&](int c) { return gray[c] * p1[c]; },          g_hsum[6] + rowOff);
    run_q([&](int c) { return gray[c] * p2[c]; },          g_hsum[7] + rowOff);
}

// ============================================================================
// K2: vertical running sums on the 8 hsum planes (float2/thread, SEG rows)
//     + fused a,b computation.
// grid = (W2/128, HH/SEG, BATCH)
// ============================================================================
__global__ __launch_bounds__(128) void k_v1() {
    const int t  = blockIdx.x * 128 + threadIdx.x;   // column-pair index
    const int b  = blockIdx.z;
    const int r0 = blockIdx.y * SEG;
    const size_t base = (size_t)b * (PLANE / 2) + t;

    float2 s[8];
#pragma unroll
    for (int q = 0; q < 8; q++) { s[q].x = 0.f; s[q].y = 0.f; }

    const int jstart = (r0 - RAD < 0) ? 0 : (r0 - RAD);
#pragma unroll 4
    for (int j = jstart; j <= r0 + RAD; j++) {
        const size_t off = base + (size_t)j * W2;
#pragma unroll
        for (int q = 0; q < 8; q++) {
            float2 v = ((const float2*)g_hsum[q])[off];
            s[q].x += v.x; s[q].y += v.y;
        }
    }

#pragma unroll 4
    for (int i = 0; i < SEG; i++) {
        const int row = r0 + i;
        const size_t off = base + (size_t)row * W2;

        float mIx = s[0].x * INV_K2, mIy = s[0].y * INV_K2;
        float cIx = s[1].x * INV_K2, cIy = s[1].y * INV_K2;
        float ivx = 1.f / (cIx - mIx * mIx + EPSV);
        float ivy = 1.f / (cIy - mIy * mIy + EPSV);
#pragma unroll
        for (int c = 0; c < 3; c++) {
            float mpx  = s[2 + c].x * INV_K2, mpy  = s[2 + c].y * INV_K2;
            float cIpx = s[5 + c].x * INV_K2, cIpy = s[5 + c].y * INV_K2;
            float ax = (cIpx - mIx * mpx) * ivx;
            float ay = (cIpy - mIy * mpy) * ivy;
            float2 av; av.x = ax; av.y = ay;
            float2 bv; bv.x = mpx - ax * mIx; bv.y = mpy - ay * mIy;
            ((float2*)g_ab[c])[off]     = av;
            ((float2*)g_ab[3 + c])[off] = bv;
        }

        const int lead  = row + RAD + 1;
        const int trail = row - RAD;
        if (lead < HH) {
            const size_t lo = base + (size_t)lead * W2;
#pragma unroll
            for (int q = 0; q < 8; q++) {
                float2 v = ((const float2*)g_hsum[q])[lo];
                s[q].x += v.x; s[q].y += v.y;
            }
        }
        if (trail >= 0) {
            const size_t to = base + (size_t)trail * W2;
#pragma unroll
            for (int q = 0; q < 8; q++) {
                float2 v = ((const float2*)g_hsum[q])[to];
                s[q].x -= v.x; s[q].y -= v.y;
            }
        }
    }
}

// ============================================================================
// K3: horizontal pass on a,b planes (plane index on blockIdx.y).
// ============================================================================
__global__ __launch_bounds__(128) void k_h2() {
    const int warp = threadIdx.x >> 5;
    const int lane = threadIdx.x & 31;
    const int grow = blockIdx.x * 4 + warp;
    const int q = blockIdx.y;

    __shared__ float s_pref[4][WW];
    float* pref = s_pref[warp];

    const size_t rowOff = (size_t)grow * WW;
    const float* __restrict__ in = g_ab[q] + rowOff;
    float* __restrict__ out = g_hsum2[q] + rowOff;

    float carry = 0.f;
#pragma unroll
    for (int i = 0; i < 16; i++) {
        int c = i * 32 + lane;
        float s = iscan(in[c], lane);
        pref[c] = s + carry;
        carry += __shfl_sync(0xffffffffu, s, 31);
    }
    __syncwarp();
#pragma unroll
    for (int i = 0; i < 16; i++) {
        int c = i * 32 + lane;
        float hi = pref[(c + RAD > WW - 1) ? (WW - 1) : (c + RAD)];
        float lo = (c >= RAD + 1) ? pref[c - RAD - 1] : 0.f;
        out[c] = hi - lo;
    }
}

// ============================================================================
// K4: vertical running sums on hsum2, SPLIT PER CHANNEL (2 planes/block)
//     + fused final output:  out[b,c] = mean_a_c * gray + mean_b_c
// grid = (W2/128, HH/SEG, BATCH*3);  blockIdx.z = b*3 + c
// ============================================================================
__global__ __launch_bounds__(128) void k_v2(float* __restrict__ out) {
    const int t  = blockIdx.x * 128 + threadIdx.x;   // column-pair index
    const int zc = blockIdx.z;
    const int b  = zc / 3;
    const int c  = zc - b * 3;
    const int r0 = blockIdx.y * SEG;
    const size_t base = (size_t)b * (PLANE / 2) + t;

    const float2* __restrict__ pa = (const float2*)g_hsum2[c];
    const float2* __restrict__ pb = (const float2*)g_hsum2[3 + c];
    const float2* __restrict__ pg = (const float2*)g_gray;
    float2* __restrict__ po = (float2*)(out + (size_t)zc * PLANE);

    float2 sa; sa.x = 0.f; sa.y = 0.f;
    float2 sb; sb.x = 0.f; sb.y = 0.f;

    const int jstart = (r0 - RAD < 0) ? 0 : (r0 - RAD);
#pragma unroll 4
    for (int j = jstart; j <= r0 + RAD; j++) {
        const size_t off = base + (size_t)j * W2;
        float2 va = pa[off], vb = pb[off];
        sa.x += va.x; sa.y += va.y;
        sb.x += vb.x; sb.y += vb.y;
    }

#pragma unroll 4
    for (int i = 0; i < SEG; i++) {
        const int row = r0 + i;
        const size_t off = base + (size_t)row * W2;
        const float2 gr = pg[off];

        float2 o;
        o.x = (sa.x * INV_K2) * gr.x + sb.x * INV_K2;
        o.y = (sa.y * INV_K2) * gr.y + sb.y * INV_K2;
        po[(size_t)row * W2 + t] = o;

        const int lead  = row + RAD + 1;
        const int trail = row - RAD;
        if (lead < HH) {
            const size_t lo = base + (size_t)lead * W2;
            float2 va = pa[lo], vb = pb[lo];
            sa.x += va.x; sa.y += va.y;
            sb.x += vb.x; sb.y += vb.y;
        }
        if (trail >= 0) {
            const size_t to = base + (size_t)trail * W2;
            float2 va = pa[to], vb = pb[to];
            sa.x -= va.x; sa.y -= va.y;
            sb.x -= vb.x; sb.y -= vb.y;
        }
    }
}

// ============================================================================
extern "C" void kernel_launch(void* const* d_in, const int* in_sizes, int n_in,
                              void* d_out, int out_size) {
    const float* guide = (const float*)d_in[0];
    const float* input = (const float*)d_in[1];
    float* out = (float*)d_out;

    k_h1<<<BATCH * HH / 4, 128>>>(guide, input);
    k_v1<<<dim3(W2 / 128, HH / SEG, BATCH), 128>>>();
    k_h2<<<dim3(BATCH * HH / 4, 6), 128>>>();
    k_v2<<<dim3(W2 / 128, HH / SEG, BATCH * 3), 128>>>(out);
}

// round 3
// speedup vs baseline: 2.1960x; 1.1951x over previous
#include <cuda_runtime.h>

#define BATCH 8
#define HH 512
#define WW 512
#define W2 (WW / 2)
#define PLANE (HH * WW)
#define NP (BATCH * PLANE)
#define RAD 15
#define INV_K2 (1.0f / 961.0f)
#define EPSV 1e-6f
#define SEG 16        // rows per vertical segment (k_v2)
#define SEGV 16       // rows per vertical segment (k_vh)

// -------- scratch (device globals) --------
// stage-1 quantities: 0=I, 1=I*I, 2..4=p_c, 5..7=I*p_c
__device__ float g_gray[NP];      // 8 MB
__device__ float g_hsum[8][NP];   // 64 MB
__device__ float g_hsum2[6][NP];  // 48 MB  (horizontal box sums of a,b)

__device__ __forceinline__ float iscan(float v, int lane) {
#pragma unroll
    for (int o = 1; o < 32; o <<= 1) {
        float n = __shfl_up_sync(0xffffffffu, v, o);
        if (lane >= o) v += n;
    }
    return v;
}

// ============================================================================
// K1: horizontal pass on stage-1 quantities (1 warp per row, 4 rows/block).
// ============================================================================
__global__ __launch_bounds__(128) void k_h1(const float* __restrict__ guide,
                                            const float* __restrict__ input) {
    const int warp = threadIdx.x >> 5;
    const int lane = threadIdx.x & 31;
    const int grow = blockIdx.x * 4 + warp;
    const int b = grow >> 9;
    const int r = grow & 511;

    const float* gR = guide + ((size_t)(b * 3 + 0) * HH + r) * WW;
    const float* gG = guide + ((size_t)(b * 3 + 1) * HH + r) * WW;
    const float* gB = guide + ((size_t)(b * 3 + 2) * HH + r) * WW;
    const float* p0 = input + ((size_t)(b * 3 + 0) * HH + r) * WW;
    const float* p1 = input + ((size_t)(b * 3 + 1) * HH + r) * WW;
    const float* p2 = input + ((size_t)(b * 3 + 2) * HH + r) * WW;

    __shared__ float s_gray[4][WW];
    __shared__ float s_pref[4][WW];
    float* gray = s_gray[warp];
    float* pref = s_pref[warp];

    const size_t rowOff = (size_t)grow * WW;

#pragma unroll
    for (int i = 0; i < 16; i++) {
        int c = i * 32 + lane;
        float v = 0.299f * gR[c] + 0.587f * gG[c] + 0.114f * gB[c];
        gray[c] = v;
        g_gray[rowOff + c] = v;
    }
    __syncwarp();

    auto run_q = [&](auto getv, float* __restrict__ outp) {
        float carry = 0.f;
#pragma unroll
        for (int i = 0; i < 16; i++) {
            int c = i * 32 + lane;
            float s = iscan(getv(c), lane);
            pref[c] = s + carry;
            carry += __shfl_sync(0xffffffffu, s, 31);
        }
        __syncwarp();
#pragma unroll
        for (int i = 0; i < 16; i++) {
            int c = i * 32 + lane;
            float hi = pref[(c + RAD > WW - 1) ? (WW - 1) : (c + RAD)];
            float lo = (c >= RAD + 1) ? pref[c - RAD - 1] : 0.f;
            outp[c] = hi - lo;
        }
        __syncwarp();
    };

    run_q([&](int c) { return gray[c]; },                  g_hsum[0] + rowOff);
    run_q([&](int c) { float g = gray[c]; return g * g; }, g_hsum[1] + rowOff);
    run_q([&](int c) { return p0[c]; },                    g_hsum[2] + rowOff);
    run_q([&](int c) { return p1[c]; },                    g_hsum[3] + rowOff);
    run_q([&](int c) { return p2[c]; },                    g_hsum[4] + rowOff);
    run_q([&](int c) { return gray[c] * p0[c]; },          g_hsum[5] + rowOff);
    run_q([&](int c) { return gray[c] * p1[c]; },          g_hsum[6] + rowOff);
    run_q([&](int c) { return gray[c] * p2[c]; },          g_hsum[7] + rowOff);
}

// ============================================================================
// K2 (fused k_v1 + k_h2): vertical running sums on 8 hsum planes, compute a,b
// in registers, block-scan horizontal box sums, write g_hsum2 directly.
// Block: 256 threads = full row width (float2/thread). grid (HH/SEGV, BATCH).
// ============================================================================
__global__ __launch_bounds__(256) void k_vh() {
    const int tid  = threadIdx.x;
    const int warp = tid >> 5;
    const int lane = tid & 31;
    const int r0 = blockIdx.x * SEGV;
    const int b  = blockIdx.y;
    const size_t base = (size_t)b * (PLANE / 2) + tid;  // float2 index

    __shared__ float s_pref[6][WW];   // 12 KB
    __shared__ float s_wtot[6][8];
    __shared__ float s_wcar[6][8];

    float2 s[8];
#pragma unroll
    for (int q = 0; q < 8; q++) { s[q].x = 0.f; s[q].y = 0.f; }

    const int jstart = (r0 - RAD < 0) ? 0 : (r0 - RAD);
#pragma unroll 4
    for (int j = jstart; j <= r0 + RAD; j++) {
        const size_t off = base + (size_t)j * W2;
#pragma unroll
        for (int q = 0; q < 8; q++) {
            float2 v = ((const float2*)g_hsum[q])[off];
            s[q].x += v.x; s[q].y += v.y;
        }
    }

    for (int i = 0; i < SEGV; i++) {
        const int row = r0 + i;
        const size_t off = base + (size_t)row * W2;

        // ---- a,b for this row (registers) ----
        float2 ab[6];
        {
            float mIx = s[0].x * INV_K2, mIy = s[0].y * INV_K2;
            float cIx = s[1].x * INV_K2, cIy = s[1].y * INV_K2;
            float ivx = 1.f / (cIx - mIx * mIx + EPSV);
            float ivy = 1.f / (cIy - mIy * mIy + EPSV);
#pragma unroll
            for (int c = 0; c < 3; c++) {
                float mpx  = s[2 + c].x * INV_K2, mpy  = s[2 + c].y * INV_K2;
                float cIpx = s[5 + c].x * INV_K2, cIpy = s[5 + c].y * INV_K2;
                float ax = (cIpx - mIx * mpx) * ivx;
                float ay = (cIpy - mIy * mpy) * ivy;
                ab[c].x = ax;                ab[c].y = ay;
                ab[3 + c].x = mpx - ax * mIx; ab[3 + c].y = mpy - ay * mIy;
            }
        }

        // ---- block-wide inclusive prefix over 512 elems, 6 quantities ----
        float tsum[6], wsc[6];
#pragma unroll
        for (int q = 0; q < 6; q++) {
            tsum[q] = ab[q].x + ab[q].y;
            wsc[q]  = iscan(tsum[q], lane);
            if (lane == 31) s_wtot[q][warp] = wsc[q];
        }
        __syncthreads();
        if (tid < 48) {
            int q = tid >> 3, w = tid & 7;
            float cacc = 0.f;
#pragma unroll
            for (int k = 0; k < 7; k++) if (k < w) cacc += s_wtot[q][k];
            s_wcar[q][w] = cacc;
        }
        __syncthreads();
#pragma unroll
        for (int q = 0; q < 6; q++) {
            float ex = wsc[q] - tsum[q] + s_wcar[q][warp];
            float px = ex + ab[q].x;
            s_pref[q][2 * tid]     = px;
            s_pref[q][2 * tid + 1] = px + ab[q].y;
        }
        __syncthreads();

        // ---- horizontal box sums -> g_hsum2 ----
        const int x0 = 2 * tid, x1 = x0 + 1;
        const int h0 = (x0 + RAD > WW - 1) ? (WW - 1) : (x0 + RAD);
        const int h1 = (x1 + RAD > WW - 1) ? (WW - 1) : (x1 + RAD);
#pragma unroll
        for (int q = 0; q < 6; q++) {
            float lo0 = (x0 >= RAD + 1) ? s_pref[q][x0 - RAD - 1] : 0.f;
            float lo1 = (x1 >= RAD + 1) ? s_pref[q][x1 - RAD - 1] : 0.f;
            float2 o;
            o.x = s_pref[q][h0] - lo0;
            o.y = s_pref[q][h1] - lo1;
            ((float2*)g_hsum2[q])[off] = o;
        }

        // ---- vertical slide ----
        const int lead  = row + RAD + 1;
        const int trail = row - RAD;
        if (lead < HH) {
            const size_t lo = base + (size_t)lead * W2;
#pragma unroll
            for (int q = 0; q < 8; q++) {
                float2 v = ((const float2*)g_hsum[q])[lo];
                s[q].x += v.x; s[q].y += v.y;
            }
        }
        if (trail >= 0) {
            const size_t to = base + (size_t)trail * W2;
#pragma unroll
            for (int q = 0; q < 8; q++) {
                float2 v = ((const float2*)g_hsum[q])[to];
                s[q].x -= v.x; s[q].y -= v.y;
            }
        }
    }
}

// ============================================================================
// K3: vertical running sums on hsum2, split per channel, fused final output.
// ============================================================================
__global__ __launch_bounds__(128) void k_v2(float* __restrict__ out) {
    const int t  = blockIdx.x * 128 + threadIdx.x;
    const int zc = blockIdx.z;
    const int b  = zc / 3;
    const int c  = zc - b * 3;
    const int r0 = blockIdx.y * SEG;
    const size_t base = (size_t)b * (PLANE / 2) + t;

    const float2* __restrict__ pa = (const float2*)g_hsum2[c];
    const float2* __restrict__ pb = (const float2*)g_hsum2[3 + c];
    const float2* __restrict__ pg = (const float2*)g_gray;
    float2* __restrict__ po = (float2*)(out + (size_t)zc * PLANE);

    float2 sa; sa.x = 0.f; sa.y = 0.f;
    float2 sb; sb.x = 0.f; sb.y = 0.f;

    const int jstart = (r0 - RAD < 0) ? 0 : (r0 - RAD);
#pragma unroll 4
    for (int j = jstart; j <= r0 + RAD; j++) {
        const size_t off = base + (size_t)j * W2;
        float2 va = pa[off], vb = pb[off];
        sa.x += va.x; sa.y += va.y;
        sb.x += vb.x; sb.y += vb.y;
    }

#pragma unroll 4
    for (int i = 0; i < SEG; i++) {
        const int row = r0 + i;
        const size_t off = base + (size_t)row * W2;
        const float2 gr = pg[off];

        float2 o;
        o.x = (sa.x * INV_K2) * gr.x + sb.x * INV_K2;
        o.y = (sa.y * INV_K2) * gr.y + sb.y * INV_K2;
        po[(size_t)row * W2 + t] = o;

        const int lead  = row + RAD + 1;
        const int trail = row - RAD;
        if (lead < HH) {
            const size_t lo = base + (size_t)lead * W2;
            float2 va = pa[lo], vb = pb[lo];
            sa.x += va.x; sa.y += va.y;
            sb.x += vb.x; sb.y += vb.y;
        }
        if (trail >= 0) {
            const size_t to = base + (size_t)trail * W2;
            float2 va = pa[to], vb = pb[to];
            sa.x -= va.x; sa.y -= va.y;
            sb.x -= vb.x; sb.y -= vb.y;
        }
    }
}

// ============================================================================
extern "C" void kernel_launch(void* const* d_in, const int* in_sizes, int n_in,
                              void* d_out, int out_size) {
    const float* guide = (const float*)d_in[0];
    const float* input = (const float*)d_in[1];
    float* out = (float*)d_out;

    k_h1<<<BATCH * HH / 4, 128>>>(guide, input);
    k_vh<<<dim3(HH / SEGV, BATCH), 256>>>();
    k_v2<<<dim3(W2 / 128, HH / SEG, BATCH * 3), 128>>>(out);
}

// round 4
// speedup vs baseline: 2.5790x; 1.1744x over previous
#include <cuda_runtime.h>

#define BATCH 8
#define HH 512
#define WW 512
#define W2 (WW / 2)
#define W4 (WW / 4)
#define PLANE (HH * WW)
#define NP (BATCH * PLANE)
#define RAD 15
#define INV_K2 (1.0f / 961.0f)
#define EPSV 1e-6f
#define SEG 16        // rows per vertical segment (k_v2)
#define SEGV 16       // rows per vertical segment (k_vh)
#define SPAD 544      // 512 + 512/16 padding
#define PADI(i) ((i) + ((i) >> 4))

// -------- scratch (device globals) --------
// stage-1 quantities: 0=I, 1=I*I, 2..4=p_c, 5..7=I*p_c
__device__ float g_gray[NP];      // 8 MB
__device__ float g_hsum[8][NP];   // 64 MB
__device__ float g_hsum2[6][NP];  // 48 MB

__device__ __forceinline__ float iscan(float v, int lane) {
#pragma unroll
    for (int o = 1; o < 32; o <<= 1) {
        float n = __shfl_up_sync(0xffffffffu, v, o);
        if (lane >= o) v += n;
    }
    return v;
}

// ============================================================================
// K1: horizontal pass, chunk-local scan. 1 warp/row, 4 rows/block.
// Thread owns 16 contiguous columns; local register prefix + one warp scan
// of chunk totals per quantity. Bank-padded smem staging.
// ============================================================================
__global__ __launch_bounds__(128) void k_h1(const float* __restrict__ guide,
                                            const float* __restrict__ input) {
    const int warp = threadIdx.x >> 5;
    const int lane = threadIdx.x & 31;
    const int grow = blockIdx.x * 4 + warp;
    const int b = grow >> 9;
    const int r = grow & 511;

    const float* gR = guide + ((size_t)(b * 3 + 0) * HH + r) * WW;
    const float* gG = guide + ((size_t)(b * 3 + 1) * HH + r) * WW;
    const float* gB = guide + ((size_t)(b * 3 + 2) * HH + r) * WW;
    const float* p0 = input + ((size_t)(b * 3 + 0) * HH + r) * WW;
    const float* p1 = input + ((size_t)(b * 3 + 1) * HH + r) * WW;
    const float* p2 = input + ((size_t)(b * 3 + 2) * HH + r) * WW;

    __shared__ float sg[4][SPAD];
    __shared__ float s0[4][SPAD];
    __shared__ float s1[4][SPAD];
    __shared__ float s2[4][SPAD];
    __shared__ float sp[4][SPAD];
    float* g  = sg[warp];
    float* q0 = s0[warp];
    float* q1 = s1[warp];
    float* q2 = s2[warp];
    float* pref = sp[warp];

    const size_t rowOff = (size_t)grow * WW;

    // stage rows (coalesced global -> padded smem), write gray plane
#pragma unroll
    for (int i = 0; i < 16; i++) {
        int c = i * 32 + lane;
        float gr = 0.299f * gR[c] + 0.587f * gG[c] + 0.114f * gB[c];
        g[PADI(c)] = gr;
        g_gray[rowOff + c] = gr;
        q0[PADI(c)] = p0[c];
        q1[PADI(c)] = p1[c];
        q2[PADI(c)] = p2[c];
    }
    __syncwarp();

    const int cb = lane * 16;
    float gv[16], pv[16], lp[16];

    auto scan_store = [&](float* __restrict__ outp) {
        float tot = lp[15];
        float ex = iscan(tot, lane) - tot;
#pragma unroll
        for (int k = 0; k < 16; k++) pref[PADI(cb + k)] = ex + lp[k];
        __syncwarp();
#pragma unroll
        for (int i = 0; i < 16; i++) {
            int x = i * 32 + lane;
            int hx = (x + RAD > WW - 1) ? (WW - 1) : (x + RAD);
            float hi = pref[PADI(hx)];
            float lo = (x >= RAD + 1) ? pref[PADI(x - RAD - 1)] : 0.f;
            outp[x] = hi - lo;
        }
        __syncwarp();
    };

    // I
    { float a = 0.f;
#pragma unroll
      for (int k = 0; k < 16; k++) { gv[k] = g[PADI(cb + k)]; a += gv[k]; lp[k] = a; } }
    scan_store(g_hsum[0] + rowOff);
    // I*I
    { float a = 0.f;
#pragma unroll
      for (int k = 0; k < 16; k++) { a += gv[k] * gv[k]; lp[k] = a; } }
    scan_store(g_hsum[1] + rowOff);
    // p0
    { float a = 0.f;
#pragma unroll
      for (int k = 0; k < 16; k++) { pv[k] = q0[PADI(cb + k)]; a += pv[k]; lp[k] = a; } }
    scan_store(g_hsum[2] + rowOff);
    // I*p0
    { float a = 0.f;
#pragma unroll
      for (int k = 0; k < 16; k++) { a += gv[k] * pv[k]; lp[k] = a; } }
    scan_store(g_hsum[5] + rowOff);
    // p1
    { float a = 0.f;
#pragma unroll
      for (int k = 0; k < 16; k++) { pv[k] = q1[PADI(cb + k)]; a += pv[k]; lp[k] = a; } }
    scan_store(g_hsum[3] + rowOff);
    // I*p1
    { float a = 0.f;
#pragma unroll
      for (int k = 0; k < 16; k++) { a += gv[k] * pv[k]; lp[k] = a; } }
    scan_store(g_hsum[6] + rowOff);
    // p2
    { float a = 0.f;
#pragma unroll
      for (int k = 0; k < 16; k++) { pv[k] = q2[PADI(cb + k)]; a += pv[k]; lp[k] = a; } }
    scan_store(g_hsum[4] + rowOff);
    // I*p2
    { float a = 0.f;
#pragma unroll
      for (int k = 0; k < 16; k++) { a += gv[k] * pv[k]; lp[k] = a; } }
    scan_store(g_hsum[7] + rowOff);
}

// ============================================================================
// K2 (fused vertical+horizontal on a,b): 256 threads = full row (float2/thr).
// 2 barriers/row, double-buffered smem, slide prefetch before scan.
// ============================================================================
__global__ __launch_bounds__(256) void k_vh() {
    const int tid  = threadIdx.x;
    const int warp = tid >> 5;
    const int lane = tid & 31;
    const int r0 = blockIdx.x * SEGV;
    const int b  = blockIdx.y;
    const size_t base = (size_t)b * (PLANE / 2) + tid;

    __shared__ float s_pref[2][6][WW];   // 24 KB
    __shared__ float s_wtot[2][6][8];

    float2 s[8];
#pragma unroll
    for (int q = 0; q < 8; q++) { s[q].x = 0.f; s[q].y = 0.f; }

    const int jstart = (r0 - RAD < 0) ? 0 : (r0 - RAD);
#pragma unroll 4
    for (int j = jstart; j <= r0 + RAD; j++) {
        const size_t off = base + (size_t)j * W2;
#pragma unroll
        for (int q = 0; q < 8; q++) {
            float2 v = ((const float2*)g_hsum[q])[off];
            s[q].x += v.x; s[q].y += v.y;
        }
    }

    for (int i = 0; i < SEGV; i++) {
        const int row = r0 + i;
        const size_t off = base + (size_t)row * W2;
        const int bu = i & 1;

        // ---- prefetch next slide loads (overlap with scan below) ----
        const int lead  = row + RAD + 1;
        const int trail = row - RAD;
        const bool hl = lead < HH;
        const bool ht = trail >= 0;
        float2 ldv[8], trv[8];
        if (hl) {
            const size_t lo = base + (size_t)lead * W2;
#pragma unroll
            for (int q = 0; q < 8; q++) ldv[q] = ((const float2*)g_hsum[q])[lo];
        }
        if (ht) {
            const size_t to = base + (size_t)trail * W2;
#pragma unroll
            for (int q = 0; q < 8; q++) trv[q] = ((const float2*)g_hsum[q])[to];
        }

        // ---- a,b for this row ----
        float2 ab[6];
        {
            float mIx = s[0].x * INV_K2, mIy = s[0].y * INV_K2;
            float cIx = s[1].x * INV_K2, cIy = s[1].y * INV_K2;
            float ivx = 1.f / (cIx - mIx * mIx + EPSV);
            float ivy = 1.f / (cIy - mIy * mIy + EPSV);
#pragma unroll
            for (int c = 0; c < 3; c++) {
                float mpx  = s[2 + c].x * INV_K2, mpy  = s[2 + c].y * INV_K2;
                float cIpx = s[5 + c].x * INV_K2, cIpy = s[5 + c].y * INV_K2;
                float ax = (cIpx - mIx * mpx) * ivx;
                float ay = (cIpy - mIy * mpy) * ivy;
                ab[c].x = ax;                 ab[c].y = ay;
                ab[3 + c].x = mpx - ax * mIx; ab[3 + c].y = mpy - ay * mIy;
            }
        }

        // ---- block prefix scan (2 barriers) ----
        float tq[6], wv[6];
#pragma unroll
        for (int q = 0; q < 6; q++) {
            tq[q] = ab[q].x + ab[q].y;
            wv[q] = iscan(tq[q], lane);
            if (lane == 31) s_wtot[bu][q][warp] = wv[q];
        }
        __syncthreads();
#pragma unroll
        for (int q = 0; q < 6; q++) {
            float carry = 0.f;
#pragma unroll
            for (int w = 0; w < 7; w++) if (w < warp) carry += s_wtot[bu][q][w];
            float ex = wv[q] - tq[q] + carry;
            float2 pr;
            pr.x = ex + ab[q].x;
            pr.y = pr.x + ab[q].y;
            ((float2*)s_pref[bu][q])[tid] = pr;
        }
        __syncthreads();

        // ---- horizontal box sums -> g_hsum2 ----
        const int x0 = 2 * tid, x1 = x0 + 1;
        const int h0 = (x0 + RAD > WW - 1) ? (WW - 1) : (x0 + RAD);
        const int h1 = (x1 + RAD > WW - 1) ? (WW - 1) : (x1 + RAD);
#pragma unroll
        for (int q = 0; q < 6; q++) {
            float lo0 = (x0 >= RAD + 1) ? s_pref[bu][q][x0 - RAD - 1] : 0.f;
            float lo1 = (x1 >= RAD + 1) ? s_pref[bu][q][x1 - RAD - 1] : 0.f;
            float2 o;
            o.x = s_pref[bu][q][h0] - lo0;
            o.y = s_pref[bu][q][h1] - lo1;
            ((float2*)g_hsum2[q])[off] = o;
        }

        // ---- apply slide ----
        if (hl) {
#pragma unroll
            for (int q = 0; q < 8; q++) { s[q].x += ldv[q].x; s[q].y += ldv[q].y; }
        }
        if (ht) {
#pragma unroll
            for (int q = 0; q < 8; q++) { s[q].x -= trv[q].x; s[q].y -= trv[q].y; }
        }
    }
}

// ============================================================================
// K3: vertical running sums on hsum2 (float4/thread), per channel, fused output.
// grid (1, HH/SEG, BATCH*3), block 128 (= full row in float4).
// ============================================================================
__global__ __launch_bounds__(128) void k_v2(float* __restrict__ out) {
    const int t  = threadIdx.x;                 // float4 column index
    const int zc = blockIdx.z;
    const int b  = zc / 3;
    const int c  = zc - b * 3;
    const int r0 = blockIdx.y * SEG;
    const size_t base = (size_t)b * (PLANE / 4) + t;

    const float4* __restrict__ pa = (const float4*)g_hsum2[c];
    const float4* __restrict__ pb = (const float4*)g_hsum2[3 + c];
    const float4* __restrict__ pg = (const float4*)g_gray;
    float4* __restrict__ po = (float4*)(out + (size_t)zc * PLANE);

    float4 sa = make_float4(0.f, 0.f, 0.f, 0.f);
    float4 sb = make_float4(0.f, 0.f, 0.f, 0.f);

    const int jstart = (r0 - RAD < 0) ? 0 : (r0 - RAD);
#pragma unroll 4
    for (int j = jstart; j <= r0 + RAD; j++) {
        const size_t off = base + (size_t)j * W4;
        float4 va = pa[off], vb = pb[off];
        sa.x += va.x; sa.y += va.y; sa.z += va.z; sa.w += va.w;
        sb.x += vb.x; sb.y += vb.y; sb.z += vb.z; sb.w += vb.w;
    }

#pragma unroll 4
    for (int i = 0; i < SEG; i++) {
        const int row = r0 + i;
        const size_t off = base + (size_t)row * W4;

        const int lead  = row + RAD + 1;
        const int trail = row - RAD;
        const bool hl = lead < HH;
        const bool ht = trail >= 0;
        float4 la, lb, ta, tb;
        if (hl) {
            const size_t lo = base + (size_t)lead * W4;
            la = pa[lo]; lb = pb[lo];
        }
        if (ht) {
            const size_t to = base + (size_t)trail * W4;
            ta = pa[to]; tb = pb[to];
        }

        const float4 gr = pg[off];
        float4 o;
        o.x = (sa.x * INV_K2) * gr.x + sb.x * INV_K2;
        o.y = (sa.y * INV_K2) * gr.y + sb.y * INV_K2;
        o.z = (sa.z * INV_K2) * gr.z + sb.z * INV_K2;
        o.w = (sa.w * INV_K2) * gr.w + sb.w * INV_K2;
        po[(size_t)row * W4 + t] = o;

        if (hl) {
            sa.x += la.x; sa.y += la.y; sa.z += la.z; sa.w += la.w;
            sb.x += lb.x; sb.y += lb.y; sb.z += lb.z; sb.w += lb.w;
        }
        if (ht) {
            sa.x -= ta.x; sa.y -= ta.y; sa.z -= ta.z; sa.w -= ta.w;
            sb.x -= tb.x; sb.y -= tb.y; sb.z -= tb.z; sb.w -= tb.w;
        }
    }
}

// ============================================================================
extern "C" void kernel_launch(void* const* d_in, const int* in_sizes, int n_in,
                              void* d_out, int out_size) {
    const float* guide = (const float*)d_in[0];
    const float* input = (const float*)d_in[1];
    float* out = (float*)d_out;

    k_h1<<<BATCH * HH / 4, 128>>>(guide, input);
    k_vh<<<dim3(HH / SEGV, BATCH), 256>>>();
    k_v2<<<dim3(1, HH / SEG, BATCH * 3), 128>>>(out);
}